// round 1
// baseline (speedup 1.0000x reference)
#include <cuda_runtime.h>

#define T 4096
#define H 4096
#define K 8
#define E 64
#define TK (T*K)        // 32768 slots
#define NBLK 32         // sort blocks of 1024 slots each

// Scratch (no cudaMalloc allowed)
__device__ int g_rank[TK];           // stable rank within (block, expert)
__device__ int g_dest[TK];           // final destination slot of source slot s
__device__ int g_blockcount[NBLK*E]; // per-block per-expert counts
__device__ int g_blockbase[NBLK*E];  // exclusive prefix over blocks, per expert
__device__ int g_expertbase[E];      // exclusive prefix over experts

// ---------------------------------------------------------------------------
// Kernel 1: per-block stable ranks + per-block expert histograms.
// 32 blocks x 1024 threads; slot s = b*1024 + tid. Warp-level match gives
// in-warp stable rank; a 64-thread scan over the 32 warp histograms gives
// the warp base within the block.
// ---------------------------------------------------------------------------
__global__ void __launch_bounds__(1024) k_rank_hist(const int* __restrict__ idx) {
    __shared__ int whist[32 * E];    // [warp][expert]
    const int tid  = threadIdx.x;
    const int b    = blockIdx.x;
    const int w    = tid >> 5;
    const int lane = tid & 31;

    for (int i = tid; i < 32 * E; i += 1024) whist[i] = 0;
    __syncthreads();

    const int s = b * 1024 + tid;
    const int e = idx[s];

    unsigned mask = __match_any_sync(0xffffffffu, e);
    const int rank_in_warp = __popc(mask & ((1u << lane) - 1u));
    const int leader = __ffs(mask) - 1;
    if (lane == leader) whist[w * E + e] = __popc(mask);
    __syncthreads();

    // Exclusive scan across warps for each expert bin (threads 0..63)
    if (tid < E) {
        int run = 0;
        #pragma unroll
        for (int ww = 0; ww < 32; ww++) {
            int c = whist[ww * E + tid];
            whist[ww * E + tid] = run;
            run += c;
        }
        g_blockcount[b * E + tid] = run;   // block total for this expert
    }
    __syncthreads();

    g_rank[s] = whist[w * E + e] + rank_in_warp;
}

// ---------------------------------------------------------------------------
// Kernel 2: single block, 64 threads. Per-expert exclusive scan over blocks,
// then exclusive scan over experts. Also emits tokens_per_expert (as float).
// ---------------------------------------------------------------------------
__global__ void k_scan(float* __restrict__ tpe_out) {
    const int e = threadIdx.x;   // 0..63
    int run = 0;
    #pragma unroll
    for (int b = 0; b < NBLK; b++) {
        int c = g_blockcount[b * E + e];
        g_blockbase[b * E + e] = run;
        run += c;
    }
    __shared__ int tot[E];
    __shared__ int base[E];
    tot[e] = run;
    __syncthreads();
    if (e == 0) {
        int acc = 0;
        #pragma unroll
        for (int i = 0; i < E; i++) { base[i] = acc; acc += tot[i]; }
    }
    __syncthreads();
    g_expertbase[e] = base[e];
    if (tpe_out) tpe_out[e] = (float)tot[e];
}

// ---------------------------------------------------------------------------
// Kernel 3: final destination slot per source slot.
// ---------------------------------------------------------------------------
__global__ void __launch_bounds__(1024) k_dest(const int* __restrict__ idx) {
    const int b = blockIdx.x;
    const int s = b * 1024 + threadIdx.x;
    const int e = idx[s];
    g_dest[s] = g_expertbase[e] + g_blockbase[b * E + e] + g_rank[s];
}

// ---------------------------------------------------------------------------
// Kernel 4: the bandwidth kernel. One block per token. Read the 16KB row
// ONCE into registers, write 8 dispatched copies + 1 weighted combined row.
// Streaming stores (never re-read) keep L2 for x.
// ---------------------------------------------------------------------------
__global__ void __launch_bounds__(256) k_main(const float4* __restrict__ x4,
                                              const float*  __restrict__ wts,
                                              float4* __restrict__ comb4,
                                              float4* __restrict__ disp4) {
    const int t   = blockIdx.x;
    const int tid = threadIdx.x;
    const int ROW4 = H / 4;          // 1024 float4 per row

    __shared__ int   sdest[K];
    __shared__ float sws;
    if (tid < K) sdest[tid] = g_dest[t * K + tid];
    if (tid == 0) {
        float s = 0.f;
        #pragma unroll
        for (int k = 0; k < K; k++) s += wts[t * K + k];
        sws = s;
    }
    __syncthreads();

    float4 v[4];
    #pragma unroll
    for (int i = 0; i < 4; i++)
        v[i] = __ldg(&x4[(size_t)t * ROW4 + tid + i * 256]);

    if (comb4) {
        const float ws = sws;
        #pragma unroll
        for (int i = 0; i < 4; i++) {
            float4 o = make_float4(v[i].x * ws, v[i].y * ws, v[i].z * ws, v[i].w * ws);
            __stcs(&comb4[(size_t)t * ROW4 + tid + i * 256], o);
        }
    }
    if (disp4) {
        #pragma unroll
        for (int k = 0; k < K; k++) {
            const size_t base = (size_t)sdest[k] * ROW4;
            #pragma unroll
            for (int i = 0; i < 4; i++)
                __stcs(&disp4[base + tid + i * 256], v[i]);
        }
    }
}

// ---------------------------------------------------------------------------
extern "C" void kernel_launch(void* const* d_in, const int* in_sizes, int n_in,
                              void* d_out, int out_size) {
    const float* x   = (const float*)d_in[0];
    const int*   idx = (const int*)  d_in[1];
    const float* w   = (const float*)d_in[2];
    float* out = (float*)d_out;

    const long long TH  = (long long)T * H;          // 16,777,216
    const long long TKH = (long long)TK * H;         // 134,217,728
    const long long os  = (long long)out_size;

    float* comb = nullptr;
    float* disp = nullptr;
    float* tpe  = nullptr;

    if (os >= TH + TKH) {
        comb = out;
        disp = out + TH;
        if (os >= TH + TKH + E) tpe = out + TH + TKH;
    } else if (os == TKH) {
        disp = out;                                  // dispatched-only layout
    } else {
        comb = out;                                  // combined-only layout
    }

    k_rank_hist<<<NBLK, 1024>>>(idx);
    k_scan<<<1, 64>>>(tpe);
    k_dest<<<NBLK, 1024>>>(idx);
    k_main<<<T, 256>>>((const float4*)x, w, (float4*)comb, (float4*)disp);
}